// round 1
// baseline (speedup 1.0000x reference)
#include <cuda_runtime.h>

namespace {
constexpr int B = 512, T = 512, D = 128, DOUT = 32, C = 4;
constexpr float ALPHA = 0.1f;
constexpr float GAMMA = 0.9f;
constexpr float EPS = 1e-5f;
constexpr float EPS_H = 1e-6f;
constexpr float LN_EPS = 1e-5f;
}

__global__ __launch_bounds__(128)
void sync_head_kernel(const float* __restrict__ z,
                      const float* __restrict__ proj,
                      const float* __restrict__ ln_w,
                      const float* __restrict__ ln_b,
                      const float* __restrict__ cls_w,
                      const float* __restrict__ cls_b,
                      float* __restrict__ x_out,
                      float* __restrict__ logits_out)
{
    const int b    = blockIdx.x;
    const int tid  = threadIdx.x;
    const int lane = tid & 31;
    const int w    = tid >> 5;

    __shared__ float red[4];
    __shared__ float psum[128];

    // proj rows for this warp's channel slice; column = lane (output j).
    float pr[32];
#pragma unroll
    for (int k = 0; k < 32; ++k)
        pr[k] = proj[(w * 32 + k) * DOUT + lane];

    float m = 0.f, m2 = 0.f;     // Welford state for channel d = tid
    float h = 0.f, s = 0.f;      // EMA state (meaningful on warp 0, lane = output j)

    const float lw  = ln_w[lane];
    const float lb  = ln_b[lane];
    const float cw0 = cls_w[0 * DOUT + lane];
    const float cw1 = cls_w[1 * DOUT + lane];
    const float cw2 = cls_w[2 * DOUT + lane];
    const float cw3 = cls_w[3 * DOUT + lane];
    const float cb  = cls_b[lane & 3];

    const float* zp = z + (size_t)b * T * D + tid;
    float* xo = x_out + (size_t)b * T * DOUT + lane;
    float* lo = logits_out + (size_t)b * T * C;

    float zcur = zp[0];

#pragma unroll 1
    for (int t = 0; t < T; ++t) {
        // prefetch next timestep while this step computes
        float znext = 0.f;
        if (t + 1 < T) znext = zp[(size_t)(t + 1) * D];

        // ---- Welford update ----
        const float tau    = (float)(t + 1);
        const float delta  = zcur - m;
        m += __fdividef(delta, tau);
        const float delta2 = zcur - m;
        m2 = fmaf(delta, delta2, m2);
        const float denom  = fmaxf(tau - 1.0f, 1.0f);
        const float v      = __fdividef(m2, denom);

        // ---- v_bar: mean of v over 128 channels ----
        float vs = v;
#pragma unroll
        for (int o = 16; o > 0; o >>= 1)
            vs += __shfl_xor_sync(0xffffffffu, vs, o);
        if (lane == 0) red[w] = vs;
        __syncthreads();
        const float v_bar = (red[0] + red[1] + red[2] + red[3]) * (1.0f / 128.0f);

        const float v_tilde = fmaf(ALPHA, v_bar, (1.0f - ALPHA) * v);
        const float zt      = delta2 * rsqrtf(v_tilde + EPS);

        // ---- partial GEMV: warp w's 32 channels -> all 32 outputs (j = lane) ----
        float p = 0.f;
#pragma unroll
        for (int k = 0; k < 32; ++k) {
            const float zk = __shfl_sync(0xffffffffu, zt, k);
            p = fmaf(zk, pr[k], p);
        }
        psum[tid] = p;
        __syncthreads();

        // ---- tail on warp 0: EMA, log, LN, classifier ----
        if (w == 0) {
            const float r = (psum[lane] + psum[lane + 32]) +
                            (psum[lane + 64] + psum[lane + 96]);
            h = fmaf(GAMMA, h, r * r);
            s = fmaf(GAMMA, s, 1.0f);
            const float x = __logf(__fdividef(h, s) + EPS_H);

            // LayerNorm over 32 lanes
            float mu = x;
#pragma unroll
            for (int o = 16; o > 0; o >>= 1)
                mu += __shfl_xor_sync(0xffffffffu, mu, o);
            mu *= (1.0f / 32.0f);
            const float xc = x - mu;
            float var = xc * xc;
#pragma unroll
            for (int o = 16; o > 0; o >>= 1)
                var += __shfl_xor_sync(0xffffffffu, var, o);
            var *= (1.0f / 32.0f);
            const float xn = fmaf(xc * rsqrtf(var + LN_EPS), lw, lb);

            // logits: 4 dot products over 32 lanes
            float l0 = xn * cw0, l1 = xn * cw1, l2 = xn * cw2, l3 = xn * cw3;
#pragma unroll
            for (int o = 16; o > 0; o >>= 1) {
                l0 += __shfl_xor_sync(0xffffffffu, l0, o);
                l1 += __shfl_xor_sync(0xffffffffu, l1, o);
                l2 += __shfl_xor_sync(0xffffffffu, l2, o);
                l3 += __shfl_xor_sync(0xffffffffu, l3, o);
            }

            xo[(size_t)t * DOUT] = x;
            if (lane < 4) {
                const float lv = (lane == 0) ? l0 : (lane == 1) ? l1
                               : (lane == 2) ? l2 : l3;
                lo[(size_t)t * C + lane] = lv + cb;
            }
        }

        zcur = znext;
    }
}

extern "C" void kernel_launch(void* const* d_in, const int* in_sizes, int n_in,
                              void* d_out, int out_size)
{
    const float* z     = (const float*)d_in[0];
    const float* proj  = (const float*)d_in[1];
    const float* ln_w  = (const float*)d_in[2];
    const float* ln_b  = (const float*)d_in[3];
    const float* cls_w = (const float*)d_in[4];
    const float* cls_b = (const float*)d_in[5];

    float* out        = (float*)d_out;
    float* x_out      = out;
    float* logits_out = out + (size_t)B * T * DOUT;

    sync_head_kernel<<<B, 128>>>(z, proj, ln_w, ln_b, cls_w, cls_b,
                                 x_out, logits_out);
}

// round 2
// speedup vs baseline: 1.5901x; 1.5901x over previous
#include <cuda_runtime.h>

namespace {
constexpr int B = 512, T = 512, D = 128, DOUT = 32, C = 4;
constexpr int NC = 8, CT = 64;              // chunks over T, chunk length
constexpr float ALPHA  = 0.1f;
constexpr float GAMMA  = 0.9f;
constexpr float EPS    = 1e-5f;
constexpr float EPS_H  = 1e-6f;
constexpr float LN_EPS = 1e-5f;
constexpr float G64    = 0.0011790184577738583f;   // 0.9^64
constexpr float LN_G   = -0.10536051565782628f;    // ln(0.9)
}

// scratch (static device globals — no allocation)
__device__ float g_c1[B * NC * D];                 // carry prefix sum of z
__device__ float g_c2[B * NC * D];                 // carry prefix sum of z^2
__device__ float g_hloc[(size_t)B * T * DOUT];     // chunk-local EMA of r^2
__device__ float g_hend[B * NC * DOUT];            // chunk-local EMA at chunk end
__device__ float g_hprev[B * NC * DOUT];           // full h at end of previous chunk

// ---------------------------------------------------------------------------
// K1: per-(b,d) prefix sums of z and z^2, written at each chunk boundary
// ---------------------------------------------------------------------------
__global__ __launch_bounds__(128)
void k_stats(const float* __restrict__ z)
{
    const int b = blockIdx.x;
    const int d = threadIdx.x;
    const float* zp = z + (size_t)b * T * D + d;

    float s1 = 0.f, s2 = 0.f;
#pragma unroll 1
    for (int c = 0; c < NC; ++c) {
        g_c1[(b * NC + c) * D + d] = s1;
        g_c2[(b * NC + c) * D + d] = s2;
#pragma unroll 8
        for (int tl = 0; tl < CT; ++tl) {
            float zz = zp[(size_t)(c * CT + tl) * D];
            s1 += zz;
            s2 = fmaf(zz, zz, s2);
        }
    }
}

// ---------------------------------------------------------------------------
// K2: per-(b,chunk) block: normalize + project + chunk-local EMA
// ---------------------------------------------------------------------------
__global__ __launch_bounds__(128)
void k_main(const float* __restrict__ z, const float* __restrict__ proj)
{
    const int c = blockIdx.x;
    const int b = blockIdx.y;
    const int tid = threadIdx.x;
    const int lane = tid & 31;
    const int w = tid >> 5;

    __shared__ float red[4];
    __shared__ float psum[128];

    // proj rows for this warp's 32-channel slice; column = lane (output j)
    float pr[32];
#pragma unroll
    for (int k = 0; k < 32; ++k)
        pr[k] = proj[(w * 32 + k) * DOUT + lane];

    float s1 = g_c1[(b * NC + c) * D + tid];
    float s2 = g_c2[(b * NC + c) * D + tid];
    float h = 0.f;   // meaningful on warp 0 (lane = output j)

    const float* zp = z + ((size_t)b * T + (size_t)c * CT) * D + tid;
    float* hl = g_hloc + ((size_t)b * T + (size_t)c * CT) * DOUT;
    const int t0 = c * CT;

    float zcur = zp[0];

#pragma unroll 1
    for (int tl = 0; tl < CT; ++tl) {
        float znext = (tl + 1 < CT) ? zp[(size_t)(tl + 1) * D] : 0.f;

        const float tau = (float)(t0 + tl + 1);
        s1 += zcur;
        s2 = fmaf(zcur, zcur, s2);
        const float m  = __fdividef(s1, tau);
        const float M2 = fmaf(-s1, m, s2);
        const float v  = __fdividef(M2, fmaxf(tau - 1.f, 1.f));

        // v_bar: mean over 128 channels
        float vs = v;
#pragma unroll
        for (int o = 16; o > 0; o >>= 1)
            vs += __shfl_xor_sync(0xffffffffu, vs, o);
        if (lane == 0) red[w] = vs;
        __syncthreads();
        const float v_bar = (red[0] + red[1] + red[2] + red[3]) * (1.f / 128.f);

        const float v_tilde = fmaf(ALPHA, v_bar, (1.f - ALPHA) * v);
        const float zt = (zcur - m) * rsqrtf(v_tilde + EPS);

        // partial GEMV: warp w's 32 channels -> all 32 outputs (j = lane)
        float p0 = 0.f, p1 = 0.f;
#pragma unroll
        for (int k = 0; k < 32; k += 2) {
            p0 = fmaf(__shfl_sync(0xffffffffu, zt, k),     pr[k],     p0);
            p1 = fmaf(__shfl_sync(0xffffffffu, zt, k + 1), pr[k + 1], p1);
        }
        psum[tid] = p0 + p1;
        __syncthreads();

        if (w == 0) {
            const float r = (psum[lane] + psum[lane + 32]) +
                            (psum[lane + 64] + psum[lane + 96]);
            h = fmaf(GAMMA, h, r * r);
            hl[(size_t)tl * DOUT + lane] = h;
        }

        zcur = znext;
    }

    if (tid < 32)
        g_hend[(b * NC + c) * DOUT + tid] = h;
}

// ---------------------------------------------------------------------------
// K3: scan chunk-end EMA values -> carry-in per chunk
// ---------------------------------------------------------------------------
__global__ __launch_bounds__(32)
void k_scan()
{
    const int b = blockIdx.x;
    const int j = threadIdx.x;
    float H = 0.f;
#pragma unroll
    for (int c = 0; c < NC; ++c) {
        g_hprev[(b * NC + c) * DOUT + j] = H;
        H = fmaf(G64, H, g_hend[(b * NC + c) * DOUT + j]);
    }
}

// ---------------------------------------------------------------------------
// K4: fully parallel tail: h reconstruction, log, LayerNorm, classifier
// one warp per (b,t); lane = output j
// ---------------------------------------------------------------------------
__global__ __launch_bounds__(256)
void k_tail(const float* __restrict__ ln_w, const float* __restrict__ ln_b,
            const float* __restrict__ cls_w, const float* __restrict__ cls_b,
            float* __restrict__ x_out, float* __restrict__ logits_out)
{
    const int gw = blockIdx.x * 8 + (threadIdx.x >> 5);   // (b*T + t)
    const int lane = threadIdx.x & 31;
    const int b = gw >> 9;          // / T
    const int t = gw & (T - 1);     // % T
    const int c  = t >> 6;          // / CT
    const int tl = t & (CT - 1);    // % CT

    const float hloc = g_hloc[((size_t)b * T + t) * DOUT + lane];
    const float Hp   = g_hprev[(b * NC + c) * DOUT + lane];

    const float gpt = __expf((float)(tl + 1) * LN_G);     // gamma^(tl+1)
    const float h   = fmaf(gpt, Hp, hloc);
    const float gt  = __expf((float)(t + 1) * LN_G);      // gamma^(t+1)
    const float s   = (1.f - gt) * (1.f / (1.f - GAMMA));

    const float x = __logf(__fdividef(h, s) + EPS_H);

    // LayerNorm over 32 lanes (single-pass mean / mean-of-squares)
    float sx = x, sxx = x * x;
#pragma unroll
    for (int o = 16; o > 0; o >>= 1) {
        sx  += __shfl_xor_sync(0xffffffffu, sx,  o);
        sxx += __shfl_xor_sync(0xffffffffu, sxx, o);
    }
    const float mu  = sx * (1.f / 32.f);
    const float var = sxx * (1.f / 32.f) - mu * mu;
    const float xn  = fmaf((x - mu) * rsqrtf(var + LN_EPS), ln_w[lane], ln_b[lane]);

    // classifier: 4 dot products over 32 lanes
    float l0 = xn * cls_w[lane];
    float l1 = xn * cls_w[32 + lane];
    float l2 = xn * cls_w[64 + lane];
    float l3 = xn * cls_w[96 + lane];
#pragma unroll
    for (int o = 16; o > 0; o >>= 1) {
        l0 += __shfl_xor_sync(0xffffffffu, l0, o);
        l1 += __shfl_xor_sync(0xffffffffu, l1, o);
        l2 += __shfl_xor_sync(0xffffffffu, l2, o);
        l3 += __shfl_xor_sync(0xffffffffu, l3, o);
    }

    x_out[((size_t)b * T + t) * DOUT + lane] = x;
    if (lane < 4) {
        const float lv = (lane == 0) ? l0 : (lane == 1) ? l1
                       : (lane == 2) ? l2 : l3;
        logits_out[((size_t)b * T + t) * C + lane] = lv + cls_b[lane];
    }
}

// ---------------------------------------------------------------------------
extern "C" void kernel_launch(void* const* d_in, const int* in_sizes, int n_in,
                              void* d_out, int out_size)
{
    const float* z     = (const float*)d_in[0];
    const float* proj  = (const float*)d_in[1];
    const float* ln_w  = (const float*)d_in[2];
    const float* ln_b  = (const float*)d_in[3];
    const float* cls_w = (const float*)d_in[4];
    const float* cls_b = (const float*)d_in[5];

    float* out        = (float*)d_out;
    float* x_out      = out;
    float* logits_out = out + (size_t)B * T * DOUT;

    k_stats<<<B, 128>>>(z);
    k_main<<<dim3(NC, B), 128>>>(z, proj);
    k_scan<<<B, 32>>>();
    k_tail<<<(B * T) / 8, 256>>>(ln_w, ln_b, cls_w, cls_b, x_out, logits_out);
}

// round 3
// speedup vs baseline: 1.6651x; 1.0471x over previous
#include <cuda_runtime.h>

namespace {
constexpr int B = 512, T = 512, D = 128, DOUT = 32, C = 4;
constexpr int NC = 16, CT = 32;             // chunks over T, chunk length
constexpr float ALPHA  = 0.1f;
constexpr float GAMMA  = 0.9f;
constexpr float EPS    = 1e-5f;
constexpr float EPS_H  = 1e-6f;
constexpr float LN_EPS = 1e-5f;
constexpr float GCT    = 0.03433683820292512f;   // 0.9^32
constexpr float LN_G   = -0.10536051565782628f;  // ln(0.9)
}

// scratch (static device globals — no allocation)
__device__ float g_c1[B * NC * D];               // chunk sums -> exclusive prefix of z
__device__ float g_c2[B * NC * D];               // chunk sums -> exclusive prefix of z^2
__device__ float g_hloc[(size_t)B * T * DOUT];   // chunk-local EMA of r^2
__device__ float g_hend[B * NC * DOUT];          // chunk-local EMA at chunk end
__device__ float g_hprev[B * NC * DOUT];         // full h at end of previous chunk

// ---------------------------------------------------------------------------
// K1: chunk-local sums of z and z^2 (fully parallel over (chunk, b))
// ---------------------------------------------------------------------------
__global__ __launch_bounds__(128)
void k_stats(const float* __restrict__ z)
{
    const int c = blockIdx.x;
    const int b = blockIdx.y;
    const int d = threadIdx.x;
    const float* zp = z + ((size_t)b * T + (size_t)c * CT) * D + d;

    float s1 = 0.f, s2 = 0.f;
#pragma unroll 8
    for (int tl = 0; tl < CT; ++tl) {
        float zz = zp[(size_t)tl * D];
        s1 += zz;
        s2 = fmaf(zz, zz, s2);
    }
    g_c1[(b * NC + c) * D + d] = s1;
    g_c2[(b * NC + c) * D + d] = s2;
}

// K1b: in-place exclusive prefix over chunks per (b, d)
__global__ __launch_bounds__(128)
void k_carry()
{
    const int b = blockIdx.x;
    const int d = threadIdx.x;
    float s1 = 0.f, s2 = 0.f;
#pragma unroll
    for (int c = 0; c < NC; ++c) {
        const int i = (b * NC + c) * D + d;
        const float t1 = g_c1[i], t2 = g_c2[i];
        g_c1[i] = s1;
        g_c2[i] = s2;
        s1 += t1;
        s2 += t2;
    }
}

// ---------------------------------------------------------------------------
// K2: per-(b,chunk): normalize + project + chunk-local EMA.
// One __syncthreads per step (double-buffered exchanges), smem-broadcast GEMV.
// ---------------------------------------------------------------------------
__global__ __launch_bounds__(128)
void k_main(const float* __restrict__ z, const float* __restrict__ proj)
{
    const int c = blockIdx.x;
    const int b = blockIdx.y;
    const int tid = threadIdx.x;
    const int lane = tid & 31;
    const int w = tid >> 5;

    __shared__ __align__(16) float red[2][4];
    __shared__ __align__(16) float zbuf[128];
    __shared__ __align__(16) float psum[2][128];

    // proj rows for this warp's 32-channel slice; column = lane (output j)
    float pr[32];
#pragma unroll
    for (int k = 0; k < 32; ++k)
        pr[k] = proj[(w * 32 + k) * DOUT + lane];

    float s1 = g_c1[(b * NC + c) * D + tid];
    float s2 = g_c2[(b * NC + c) * D + tid];
    float h = 0.f;
    const int t0 = c * CT;

    const float* zp = z + ((size_t)b * T + (size_t)t0) * D + tid;
    float* hl = g_hloc + ((size_t)b * T + (size_t)t0) * DOUT;

    // ---- prologue: welford + v-reduction for step 0 ----
    float zcur = zp[0];
    float v, delta2;
    {
        const float tau = (float)(t0 + 1);
        s1 += zcur;
        s2 = fmaf(zcur, zcur, s2);
        const float m = s1 * __frcp_rn(tau);
        const float M2 = fmaf(-s1, m, s2);
        v = M2 * __frcp_rn(fmaxf(tau - 1.f, 1.f));
        delta2 = zcur - m;
        float vs = v;
#pragma unroll
        for (int o = 16; o > 0; o >>= 1)
            vs += __shfl_xor_sync(0xffffffffu, vs, o);
        if (lane == 0) red[0][w] = vs;
    }
    __syncthreads();

#pragma unroll 1
    for (int tl = 0; tl < CT; ++tl) {
        const int buf = tl & 1;

        // prefetch next z
        float znext = (tl + 1 < CT) ? zp[(size_t)(tl + 1) * D] : 0.f;

        // v_bar for this step (exchanged before last barrier)
        const float4 rv = *(const float4*)red[buf];
        const float v_bar = ((rv.x + rv.y) + (rv.z + rv.w)) * (1.f / 128.f);
        const float v_tilde = fmaf(ALPHA, v_bar, (1.f - ALPHA) * v);
        const float zt = delta2 * rsqrtf(v_tilde + EPS);

        // publish zt within own warp, then 8x LDS.128 broadcast GEMV
        zbuf[tid] = zt;
        __syncwarp();
        float p0 = 0.f, p1 = 0.f, p2 = 0.f, p3 = 0.f;
        const float4* zb4 = (const float4*)(zbuf + w * 32);
#pragma unroll
        for (int i = 0; i < 8; ++i) {
            const float4 za = zb4[i];
            p0 = fmaf(za.x, pr[4 * i + 0], p0);
            p1 = fmaf(za.y, pr[4 * i + 1], p1);
            p2 = fmaf(za.z, pr[4 * i + 2], p2);
            p3 = fmaf(za.w, pr[4 * i + 3], p3);
        }
        psum[buf][tid] = (p0 + p1) + (p2 + p3);

        // welford + v-reduction for NEXT step (before the single barrier)
        if (tl + 1 < CT) {
            zcur = znext;
            const float tau = (float)(t0 + tl + 2);
            s1 += zcur;
            s2 = fmaf(zcur, zcur, s2);
            const float m = s1 * __frcp_rn(tau);
            const float M2 = fmaf(-s1, m, s2);
            v = M2 * __frcp_rn(tau - 1.f);
            delta2 = zcur - m;
            float vs = v;
#pragma unroll
            for (int o = 16; o > 0; o >>= 1)
                vs += __shfl_xor_sync(0xffffffffu, vs, o);
            if (lane == 0) red[buf ^ 1][w] = vs;
        }

        __syncthreads();

        // combine psums (all warps redundantly; warp 0 stores)
        const float r = (psum[buf][lane] + psum[buf][lane + 32]) +
                        (psum[buf][lane + 64] + psum[buf][lane + 96]);
        h = fmaf(GAMMA, h, r * r);
        if (w == 0)
            hl[(size_t)tl * DOUT + lane] = h;
    }

    if (tid < 32)
        g_hend[(b * NC + c) * DOUT + tid] = h;
}

// ---------------------------------------------------------------------------
// K3: scan chunk-end EMA values -> carry-in per chunk
// ---------------------------------------------------------------------------
__global__ __launch_bounds__(32)
void k_scan()
{
    const int b = blockIdx.x;
    const int j = threadIdx.x;
    float H = 0.f;
#pragma unroll
    for (int c = 0; c < NC; ++c) {
        g_hprev[(b * NC + c) * DOUT + j] = H;
        H = fmaf(GCT, H, g_hend[(b * NC + c) * DOUT + j]);
    }
}

// ---------------------------------------------------------------------------
// K4: fully parallel tail: h reconstruction, log, LayerNorm, classifier.
// One warp per (b,t); lane = output j.
// ---------------------------------------------------------------------------
__global__ __launch_bounds__(256)
void k_tail(const float* __restrict__ ln_w, const float* __restrict__ ln_b,
            const float* __restrict__ cls_w, const float* __restrict__ cls_b,
            float* __restrict__ x_out, float* __restrict__ logits_out)
{
    const int gw = blockIdx.x * 8 + (threadIdx.x >> 5);   // (b*T + t)
    const int lane = threadIdx.x & 31;
    const int b = gw >> 9;
    const int t = gw & (T - 1);
    const int c  = t >> 5;          // / CT
    const int tl = t & (CT - 1);    // % CT

    const float hloc = g_hloc[((size_t)b * T + t) * DOUT + lane];
    const float Hp   = g_hprev[(b * NC + c) * DOUT + lane];

    const float gpt = __expf((float)(tl + 1) * LN_G);     // gamma^(tl+1)
    const float h   = fmaf(gpt, Hp, hloc);
    const float gt  = __expf((float)(t + 1) * LN_G);      // gamma^(t+1)
    const float s   = (1.f - gt) * (1.f / (1.f - GAMMA));

    const float x = __logf(__fdividef(h, s) + EPS_H);

    // LayerNorm over 32 lanes
    float sx = x, sxx = x * x;
#pragma unroll
    for (int o = 16; o > 0; o >>= 1) {
        sx  += __shfl_xor_sync(0xffffffffu, sx,  o);
        sxx += __shfl_xor_sync(0xffffffffu, sxx, o);
    }
    const float mu  = sx * (1.f / 32.f);
    const float var = sxx * (1.f / 32.f) - mu * mu;
    const float xn  = fmaf((x - mu) * rsqrtf(var + LN_EPS), ln_w[lane], ln_b[lane]);

    // classifier: 4 dot products over 32 lanes, shared-butterfly form (14 shfl)
    float l0 = xn * cls_w[lane];
    float l1 = xn * cls_w[32 + lane];
    float l2 = xn * cls_w[64 + lane];
    float l3 = xn * cls_w[96 + lane];
#pragma unroll
    for (int o = 16; o >= 4; o >>= 1) {
        l0 += __shfl_xor_sync(0xffffffffu, l0, o);
        l1 += __shfl_xor_sync(0xffffffffu, l1, o);
        l2 += __shfl_xor_sync(0xffffffffu, l2, o);
        l3 += __shfl_xor_sync(0xffffffffu, l3, o);
    }
    // lane l (< 16): holds partials over residue class (l&3); pick logit a = l>>2
    const int a = (lane >> 2) & 3;
    float q = (a == 0) ? l0 : (a == 1) ? l1 : (a == 2) ? l2 : l3;
    q += __shfl_xor_sync(0xffffffffu, q, 1);
    q += __shfl_xor_sync(0xffffffffu, q, 2);
    // lanes 0,4,8,12 now hold full logits 0..3

    x_out[((size_t)b * T + t) * DOUT + lane] = x;
    if (lane < 16 && (lane & 3) == 0)
        logits_out[((size_t)b * T + t) * C + a] = q + cls_b[a];
}

// ---------------------------------------------------------------------------
extern "C" void kernel_launch(void* const* d_in, const int* in_sizes, int n_in,
                              void* d_out, int out_size)
{
    const float* z     = (const float*)d_in[0];
    const float* proj  = (const float*)d_in[1];
    const float* ln_w  = (const float*)d_in[2];
    const float* ln_b  = (const float*)d_in[3];
    const float* cls_w = (const float*)d_in[4];
    const float* cls_b = (const float*)d_in[5];

    float* out        = (float*)d_out;
    float* x_out      = out;
    float* logits_out = out + (size_t)B * T * DOUT;

    k_stats<<<dim3(NC, B), 128>>>(z);
    k_carry<<<B, 128>>>();
    k_main<<<dim3(NC, B), 128>>>(z, proj);
    k_scan<<<B, 32>>>();
    k_tail<<<(B * T) / 8, 256>>>(ln_w, ln_b, cls_w, cls_b, x_out, logits_out);
}

// round 5
// speedup vs baseline: 1.7969x; 1.0792x over previous
#include <cuda_runtime.h>
#include <cstdint>

namespace {
constexpr int B = 512, T = 512, D = 128, DOUT = 32, C = 4;
constexpr int NCB = 4;      // chunks over T
constexpr int CTB = 128;    // timesteps per block
constexpr int SUB = 32;     // sub-tile of timesteps
constexpr int NSUB = CTB / SUB;
constexpr float ALPHA  = 0.1f;
constexpr float GAMMA  = 0.9f;
constexpr float EPS    = 1e-5f;
constexpr float EPS_H  = 1e-6f;
constexpr float LN_EPS = 1e-5f;
constexpr float NLN_G  = 0.10536051565782628f;   // -ln(0.9)

// smem layout (floats)
constexpr int OFF_ZS   = 0;                  // [32][132] delta2 -> z_tilde
constexpr int OFF_VS   = OFF_ZS + 32 * 132;  // [32][132] v
constexpr int OFF_PT   = OFF_VS + 32 * 132;  // [32][132] proj^T (pT[j][d])
constexpr int OFF_R2   = OFF_PT + 32 * 132;  // [128][36]  r^2
constexpr int OFF_VBAR = OFF_R2 + 128 * 36;  // [32]
constexpr int OFF_WTOT = OFF_VBAR + 32;      // [4][32]
constexpr int OFF_HP   = OFF_WTOT + 128;     // [32]
constexpr int OFF_LNW  = OFF_HP + 32;        // [32]
constexpr int OFF_LNB  = OFF_LNW + 32;       // [32]
constexpr int OFF_CW   = OFF_LNB + 32;       // [4][32]
constexpr int OFF_CB   = OFF_CW + 128;       // [4]
constexpr int SMEM_FLOATS = OFF_CB + 4;
constexpr int SMEM_BYTES  = SMEM_FLOATS * 4; // 70672 B
}

// scratch (static device globals — no allocation)
__device__ float g_s1[B * NCB * D];
__device__ float g_s2[B * NCB * D];
__device__ float g_hfull[B * NCB * DOUT];
__device__ int   g_flag[B * NCB];

// packed f32x2 FMA (Blackwell): d = a*b + c elementwise on 2 floats
__device__ __forceinline__ void fma2(unsigned long long& d,
                                     unsigned long long a,
                                     unsigned long long b,
                                     unsigned long long c)
{
    asm("fma.rn.f32x2 %0, %1, %2, %3;" : "=l"(d) : "l"(a), "l"(b), "l"(c));
}
__device__ __forceinline__ float lo32(unsigned long long p) {
    return __uint_as_float((unsigned)(p & 0xffffffffull));
}
__device__ __forceinline__ float hi32(unsigned long long p) {
    return __uint_as_float((unsigned)(p >> 32));
}

// ---------------------------------------------------------------------------
// K1: per-(b,chunk) sums of z, z^2 (for Welford carry) + flag reset
// ---------------------------------------------------------------------------
__global__ __launch_bounds__(128)
void k_stats(const float* __restrict__ z)
{
    const int b = blockIdx.x, c = blockIdx.y, d = threadIdx.x;
    const float* zp = z + ((size_t)(b * T + c * CTB)) * D + d;
    float s1 = 0.f, s2 = 0.f;
#pragma unroll 4
    for (int t = 0; t < CTB; ++t) {
        float zz = zp[(size_t)t * D];
        s1 += zz;
        s2 = fmaf(zz, zz, s2);
    }
    g_s1[(b * NCB + c) * D + d] = s1;
    g_s2[(b * NCB + c) * D + d] = s2;
    if (d == 0) g_flag[b * NCB + c] = 0;
}

// ---------------------------------------------------------------------------
// K2: fused normalize + project + h-prefix + tail, block per (b, 128-t chunk)
// ---------------------------------------------------------------------------
__global__ __launch_bounds__(128)
void k_fused(const float* __restrict__ z, const float* __restrict__ proj,
             const float* __restrict__ ln_w, const float* __restrict__ ln_b,
             const float* __restrict__ cls_w, const float* __restrict__ cls_b,
             float* __restrict__ x_out, float* __restrict__ logits_out)
{
    const int b = blockIdx.x, c = blockIdx.y;
    const int tid = threadIdx.x, lane = tid & 31, w = tid >> 5;

    extern __shared__ float sm[];
    float* zs   = sm + OFF_ZS;
    float* vsm  = sm + OFF_VS;
    float* pT   = sm + OFF_PT;
    float* r2   = sm + OFF_R2;
    float* vbar = sm + OFF_VBAR;
    float* wtot = sm + OFF_WTOT;
    float* hps  = sm + OFF_HP;
    float* lnw  = sm + OFF_LNW;
    float* lnb  = sm + OFF_LNB;
    float* cw   = sm + OFF_CW;
    float* cb   = sm + OFF_CB;

    // ---- load proj^T + params into smem ----
    for (int idx = tid; idx < D * DOUT; idx += 128) {
        int dd = idx >> 5, j = idx & 31;
        pT[j * 132 + dd] = proj[idx];
    }
    if (tid < 32) { lnw[tid] = ln_w[tid]; lnb[tid] = ln_b[tid]; }
    if (tid < 128) cw[tid] = cls_w[tid];
    if (tid < 4) cb[tid] = cls_b[tid];

    // ---- Welford carry-in from chunk sums ----
    float s1 = 0.f, s2 = 0.f;
    for (int cp = 0; cp < c; ++cp) {
        s1 += g_s1[(b * NCB + cp) * D + tid];
        s2 += g_s2[(b * NCB + cp) * D + tid];
    }
    const int t0 = c * CTB;
    const float* zp = z + ((size_t)(b * T + t0)) * D + tid;

    const int tq = tid >> 2, jq = tid & 3;   // phase-2 mapping
    __syncthreads();

    for (int sub = 0; sub < NSUB; ++sub) {
        // ---- phase1: welford (thread = d) -> delta2, v tiles ----
#pragma unroll 4
        for (int tl = 0; tl < SUB; ++tl) {
            const int tb = sub * SUB + tl;
            const float zz = zp[(size_t)tb * D];
            const float tau = (float)(t0 + tb + 1);
            s1 += zz;
            s2 = fmaf(zz, zz, s2);
            const float m  = __fdividef(s1, tau);
            const float d2 = zz - m;
            const float M2 = fmaf(-s1, m, s2);
            const float v  = __fdividef(M2, fmaxf(tau - 1.f, 1.f));
            zs[tl * 132 + tid]  = d2;
            vsm[tl * 132 + tid] = v;
        }
        __syncthreads();

        // ---- phase1b: vbar per t (4 threads per t) ----
        {
            float p = 0.f;
            const float4* vr = (const float4*)(vsm + tq * 132) + jq * 8;
#pragma unroll
            for (int i = 0; i < 8; ++i) {
                const float4 q4 = vr[i];
                p += (q4.x + q4.y) + (q4.z + q4.w);
            }
            p += __shfl_xor_sync(0xffffffffu, p, 1);
            p += __shfl_xor_sync(0xffffffffu, p, 2);
            if (jq == 0) vbar[tq] = p * (1.f / 128.f);
        }
        __syncthreads();

        // ---- phase1c: scale delta2 -> z_tilde in place ----
#pragma unroll 4
        for (int tl = 0; tl < SUB; ++tl) {
            const float v  = vsm[tl * 132 + tid];
            const float vb = vbar[tl];
            const float vt = fmaf(ALPHA, vb, (1.f - ALPHA) * v);
            zs[tl * 132 + tid] *= rsqrtf(vt + EPS);
        }
        __syncthreads();

        // ---- phase2: GEMV 32t x 32j with packed f32x2 FMA ----
        // thread = (tq = t within sub, jq); outputs j = jq + 4*jj
        {
            unsigned long long acc[8];
#pragma unroll
            for (int jj = 0; jj < 8; ++jj) acc[jj] = 0ull;
            const ulonglong2* za2 = (const ulonglong2*)(zs + tq * 132);
#pragma unroll 4
            for (int i = 0; i < 32; ++i) {
                const ulonglong2 za = za2[i];
#pragma unroll
                for (int jj = 0; jj < 8; ++jj) {
                    const ulonglong2 pv =
                        *((const ulonglong2*)(pT + (jq + 4 * jj) * 132) + i);
                    fma2(acc[jj], za.x, pv.x, acc[jj]);
                    fma2(acc[jj], za.y, pv.y, acc[jj]);
                }
            }
            const int tb = sub * SUB + tq;
#pragma unroll
            for (int jj = 0; jj < 8; ++jj) {
                const float r = lo32(acc[jj]) + hi32(acc[jj]);
                r2[tb * 36 + jq + 4 * jj] = r * r;
            }
        }
        __syncthreads();
    }

    // ---- phase3: thread = local t; all 32 j in registers ----
    const int lt = tid;
    float a[32];
    {
        const float4* rr = (const float4*)(r2 + lt * 36);
#pragma unroll
        for (int i = 0; i < 8; ++i) {
            const float4 q4 = rr[i];
            a[4 * i] = q4.x; a[4 * i + 1] = q4.y;
            a[4 * i + 2] = q4.z; a[4 * i + 3] = q4.w;
        }
    }
    const float gu = __expf((float)lt * NLN_G);   // gamma^{-lt}
#pragma unroll
    for (int j = 0; j < 32; ++j) a[j] *= gu;

    // intra-warp inclusive prefix (per j) of u = r^2 * gamma^{-t}
#pragma unroll
    for (int j = 0; j < 32; ++j) {
        float v = a[j];
#pragma unroll
        for (int o = 1; o < 32; o <<= 1) {
            const float n = __shfl_up_sync(0xffffffffu, v, o);
            if (lane >= o) v += n;
        }
        a[j] = v;
    }
    if (lane == 31) {
        float4* wt = (float4*)(wtot + w * 32);
#pragma unroll
        for (int i = 0; i < 8; ++i)
            wt[i] = make_float4(a[4 * i], a[4 * i + 1], a[4 * i + 2], a[4 * i + 3]);
    }
    // spin for previous chunk's full h (decoupled lookback; c is slow bid index)
    if (c > 0 && tid == 0) {
        volatile int* f = (volatile int*)&g_flag[b * NCB + c - 1];
        while (*f == 0) { __nanosleep(40); }
    }
    __syncthreads();
    if (tid < 32)
        hps[tid] = (c > 0) ? g_hfull[(b * NCB + c - 1) * DOUT + tid] : 0.f;
    __syncthreads();

    // cross-warp prefix carry
#pragma unroll
    for (int wp = 0; wp < 3; ++wp) {
        if (w > wp) {
            const float4* wt = (const float4*)(wtot + wp * 32);
#pragma unroll
            for (int i = 0; i < 8; ++i) {
                const float4 q4 = wt[i];
                a[4 * i] += q4.x; a[4 * i + 1] += q4.y;
                a[4 * i + 2] += q4.z; a[4 * i + 3] += q4.w;
            }
        }
    }

    const float gl  = __expf(-(float)lt * NLN_G);   // gamma^{lt}
    const float gl1 = gl * GAMMA;                   // gamma^{lt+1}
    const int   tg  = t0 + lt;
    const float sden = (1.f - __expf(-(float)(tg + 1) * NLN_G)) * (1.f / (1.f - GAMMA));
    const float sinv = __fdividef(1.f, sden);

#pragma unroll
    for (int j = 0; j < 32; ++j)
        a[j] = fmaf(gl, a[j], gl1 * hps[j]);        // full h_t[j]

    // publish chunk-final h for the next chunk
    if (tid == 127) {
        float4* hout = (float4*)&g_hfull[(b * NCB + c) * DOUT];
#pragma unroll
        for (int i = 0; i < 8; ++i)
            hout[i] = make_float4(a[4 * i], a[4 * i + 1], a[4 * i + 2], a[4 * i + 3]);
        __threadfence();
        atomicExch(&g_flag[b * NCB + c], 1);
    }

    // x = log(h/s + eps_h)
#pragma unroll
    for (int j = 0; j < 32; ++j)
        a[j] = __logf(fmaf(a[j], sinv, EPS_H));

    // LayerNorm over 32 register values (lane-local)
    float mu = 0.f;
#pragma unroll
    for (int j = 0; j < 32; ++j) mu += a[j];
    mu *= (1.f / 32.f);
    float var = 0.f;
#pragma unroll
    for (int j = 0; j < 32; ++j) { const float dd = a[j] - mu; var = fmaf(dd, dd, var); }
    var *= (1.f / 32.f);
    const float rs = rsqrtf(var + LN_EPS);

    float l0 = 0.f, l1 = 0.f, l2 = 0.f, l3 = 0.f;
#pragma unroll
    for (int j = 0; j < 32; ++j) {
        const float xn = fmaf((a[j] - mu) * rs, lnw[j], lnb[j]);
        l0 = fmaf(xn, cw[j], l0);
        l1 = fmaf(xn, cw[32 + j], l1);
        l2 = fmaf(xn, cw[64 + j], l2);
        l3 = fmaf(xn, cw[96 + j], l3);
    }

    // stores (fully coalesced: consecutive threads = consecutive t rows)
    float4* xo = (float4*)(x_out + ((size_t)(b * T + tg)) * DOUT);
#pragma unroll
    for (int i = 0; i < 8; ++i)
        xo[i] = make_float4(a[4 * i], a[4 * i + 1], a[4 * i + 2], a[4 * i + 3]);
    float4* lo = (float4*)(logits_out + ((size_t)(b * T + tg)) * C);
    lo[0] = make_float4(l0 + cb[0], l1 + cb[1], l2 + cb[2], l3 + cb[3]);
}

// ---------------------------------------------------------------------------
extern "C" void kernel_launch(void* const* d_in, const int* in_sizes, int n_in,
                              void* d_out, int out_size)
{
    const float* z     = (const float*)d_in[0];
    const float* proj  = (const float*)d_in[1];
    const float* ln_w  = (const float*)d_in[2];
    const float* ln_b  = (const float*)d_in[3];
    const float* cls_w = (const float*)d_in[4];
    const float* cls_b = (const float*)d_in[5];

    float* out        = (float*)d_out;
    float* x_out      = out;
    float* logits_out = out + (size_t)B * T * DOUT;

    cudaFuncSetAttribute(k_fused, cudaFuncAttributeMaxDynamicSharedMemorySize,
                         SMEM_BYTES);

    k_stats<<<dim3(B, NCB), 128>>>(z);
    k_fused<<<dim3(B, NCB), 128, SMEM_BYTES>>>(z, proj, ln_w, ln_b, cls_w, cls_b,
                                               x_out, logits_out);
}

// round 6
// speedup vs baseline: 2.4620x; 1.3702x over previous
#include <cuda_runtime.h>
#include <cstdint>

namespace {
constexpr int B = 512, T = 512, D = 128, DOUT = 32, C = 4;
constexpr int NCB = 4;      // chunks over T
constexpr int CTB = 128;    // timesteps per block
constexpr int SUB = 32;     // timesteps per sub-tile
constexpr int NSUB = CTB / SUB;
constexpr float ALPHA  = 0.1f;
constexpr float GAMMA  = 0.9f;
constexpr float EPS    = 1e-5f;
constexpr float EPS_H  = 1e-6f;
constexpr float LN_EPS = 1e-5f;
constexpr float NLN_G  = 0.10536051565782628f;   // -ln(0.9)

constexpr int ZROW = 132;
// smem layout (floats)
constexpr int OFF_ZS   = 0;                   // [SUB][ZROW] delta2 -> z_tilde
constexpr int OFF_PS   = OFF_ZS + SUB * ZROW; // [SUB][ZROW] v-tile, then psum
constexpr int OFF_R2   = OFF_PS + SUB * ZROW; // [CTB][36] r^2
constexpr int OFF_VBAR = OFF_R2 + CTB * 36;   // [32]
constexpr int OFF_WTOT = OFF_VBAR + 32;       // [4][32]
constexpr int OFF_HP   = OFF_WTOT + 128;      // [32]
constexpr int OFF_LNW  = OFF_HP + 32;         // [32]
constexpr int OFF_LNB  = OFF_LNW + 32;        // [32]
constexpr int OFF_CW   = OFF_LNB + 32;        // [4][32]
constexpr int OFF_CB   = OFF_CW + 128;        // [4]
constexpr int OFF_IT   = OFF_CB + 4;          // [CTB] 1/tau
constexpr int OFF_IT1  = OFF_IT + CTB;        // [CTB] 1/max(tau-1,1)
constexpr int SMEM_FLOATS = OFF_IT1 + CTB;
constexpr int SMEM_BYTES  = SMEM_FLOATS * 4;  // ~54.8 KB
}

// scratch (static device globals — no allocation)
__device__ float g_s1[B * NCB * D];
__device__ float g_s2[B * NCB * D];
__device__ float g_hfull[B * NCB * DOUT];
__device__ int   g_flag[B * NCB];

__device__ __forceinline__ void fma2(unsigned long long& d,
                                     unsigned long long a,
                                     unsigned long long b,
                                     unsigned long long c)
{
    asm("fma.rn.f32x2 %0, %1, %2, %3;" : "=l"(d) : "l"(a), "l"(b), "l"(c));
}
__device__ __forceinline__ float lo32(unsigned long long p) {
    return __uint_as_float((unsigned)(p & 0xffffffffull));
}
__device__ __forceinline__ float hi32(unsigned long long p) {
    return __uint_as_float((unsigned)(p >> 32));
}
__device__ __forceinline__ unsigned long long pack2(float a, float b) {
    return (unsigned long long)__float_as_uint(a) |
           ((unsigned long long)__float_as_uint(b) << 32);
}

// ---------------------------------------------------------------------------
// K1: per-(b,chunk) sums of z, z^2 (Welford carry) + flag reset
// ---------------------------------------------------------------------------
__global__ __launch_bounds__(128)
void k_stats(const float* __restrict__ z)
{
    const int b = blockIdx.x, c = blockIdx.y, d = threadIdx.x;
    const float* zp = z + ((size_t)(b * T + c * CTB)) * D + d;
    float s1 = 0.f, s2 = 0.f;
#pragma unroll 4
    for (int t = 0; t < CTB; ++t) {
        float zz = zp[(size_t)t * D];
        s1 += zz;
        s2 = fmaf(zz, zz, s2);
    }
    g_s1[(b * NCB + c) * D + d] = s1;
    g_s2[(b * NCB + c) * D + d] = s2;
    if (d == 0) g_flag[b * NCB + c] = 0;
}

// ---------------------------------------------------------------------------
// K2: fused normalize + project + h-prefix + tail; block per (b, 128-t chunk)
// ---------------------------------------------------------------------------
__global__ __launch_bounds__(128)
void k_fused(const float* __restrict__ z, const float* __restrict__ proj,
             const float* __restrict__ ln_w, const float* __restrict__ ln_b,
             const float* __restrict__ cls_w, const float* __restrict__ cls_b,
             float* __restrict__ x_out, float* __restrict__ logits_out)
{
    const int b = blockIdx.x, c = blockIdx.y;
    const int tid = threadIdx.x, lane = tid & 31, w = tid >> 5;

    extern __shared__ float sm[];
    float* zs   = sm + OFF_ZS;
    float* ps   = sm + OFF_PS;     // v-tile during phase1/1b/1c, psum in phase2
    float* r2   = sm + OFF_R2;
    float* vbar = sm + OFF_VBAR;
    float* wtot = sm + OFF_WTOT;
    float* hps  = sm + OFF_HP;
    float* lnw  = sm + OFF_LNW;
    float* lnb  = sm + OFF_LNB;
    float* cw   = sm + OFF_CW;
    float* cb   = sm + OFF_CB;
    float* itab = sm + OFF_IT;
    float* itab1= sm + OFF_IT1;

    const int t0 = c * CTB;

    // ---- proj into registers, packed f32x2: pr2[i] = (proj[2i][j], proj[2i+1][j])
    // for this warp's d-slice, j = lane
    unsigned long long pr2[16];
#pragma unroll
    for (int i = 0; i < 16; ++i) {
        const float pa = proj[(w * 32 + 2 * i) * DOUT + lane];
        const float pb = proj[(w * 32 + 2 * i + 1) * DOUT + lane];
        pr2[i] = pack2(pa, pb);
    }

    // ---- params + 1/tau tables ----
    if (tid < 32) { lnw[tid] = ln_w[tid]; lnb[tid] = ln_b[tid]; }
    cw[tid] = cls_w[tid];
    if (tid < 4) cb[tid] = cls_b[tid];
    {
        const float tau = (float)(t0 + tid + 1);
        itab[tid]  = 1.0f / tau;
        itab1[tid] = 1.0f / fmaxf(tau - 1.f, 1.f);
    }

    // ---- Welford carry-in from chunk sums ----
    float s1 = 0.f, s2 = 0.f;
    for (int cp = 0; cp < c; ++cp) {
        s1 += g_s1[(b * NCB + cp) * D + tid];
        s2 += g_s2[(b * NCB + cp) * D + tid];
    }
    const float* zp = z + ((size_t)(b * T + t0)) * D + tid;

    const int tq = tid >> 2, jq = tid & 3;
    __syncthreads();

    for (int sub = 0; sub < NSUB; ++sub) {
        // ---- phase1: Welford (thread = d) -> delta2, v tiles ----
#pragma unroll 8
        for (int tl = 0; tl < SUB; ++tl) {
            const int tb = sub * SUB + tl;
            const float zz = zp[(size_t)tb * D];
            s1 += zz;
            s2 = fmaf(zz, zz, s2);
            const float m  = s1 * itab[tb];
            const float d2 = zz - m;
            const float v  = fmaf(-s1, m, s2) * itab1[tb];
            zs[tl * ZROW + tid] = d2;
            ps[tl * ZROW + tid] = v;
        }
        __syncthreads();

        // ---- phase1b: vbar per t (4 threads per t) ----
        {
            float p = 0.f;
            const float4* vr = (const float4*)(ps + tq * ZROW + jq * 32);
#pragma unroll
            for (int i = 0; i < 8; ++i) {
                const float4 q4 = vr[i];
                p += (q4.x + q4.y) + (q4.z + q4.w);
            }
            p += __shfl_xor_sync(0xffffffffu, p, 1);
            p += __shfl_xor_sync(0xffffffffu, p, 2);
            if (jq == 0) vbar[tq] = p * (1.f / 128.f);
        }
        __syncthreads();

        // ---- phase1c: scale delta2 -> z_tilde in place ----
#pragma unroll 8
        for (int tl = 0; tl < SUB; ++tl) {
            const float v  = ps[tl * ZROW + tid];
            const float vb = vbar[tl];
            const float vt = fmaf(ALPHA, vb, (1.f - ALPHA) * v);
            zs[tl * ZROW + tid] *= rsqrtf(vt + EPS);
        }
        __syncthreads();

        // ---- phase2: GEMV, proj in registers, broadcast z reads ----
        // warp w: d-slice [32w,32w+32), lane = output j; per t: 8 LDS.128 + 16 fma2
#pragma unroll 2
        for (int t = 0; t < SUB; ++t) {
            const ulonglong2* zr = (const ulonglong2*)(zs + t * ZROW + w * 32);
            unsigned long long a0 = 0ull, a1 = 0ull;
#pragma unroll
            for (int i = 0; i < 8; ++i) {
                const ulonglong2 q = zr[i];
                fma2(a0, q.x, pr2[2 * i],     a0);
                fma2(a1, q.y, pr2[2 * i + 1], a1);
            }
            ps[t * ZROW + tid] = (lo32(a0) + hi32(a0)) + (lo32(a1) + hi32(a1));
        }
        __syncthreads();

        // ---- phase2b: reduce 4 warp partials -> r^2 ----
        {
            const int j0 = jq * 8;
            float rl[8];
#pragma unroll
            for (int i = 0; i < 8; ++i) rl[i] = 0.f;
#pragma unroll
            for (int ws = 0; ws < 4; ++ws) {
                const float4* p4 = (const float4*)(ps + tq * ZROW + ws * 32 + j0);
                const float4 q0 = p4[0], q1 = p4[1];
                rl[0] += q0.x; rl[1] += q0.y; rl[2] += q0.z; rl[3] += q0.w;
                rl[4] += q1.x; rl[5] += q1.y; rl[6] += q1.z; rl[7] += q1.w;
            }
            float4* ro = (float4*)(r2 + (sub * SUB + tq) * 36 + j0);
            ro[0] = make_float4(rl[0]*rl[0], rl[1]*rl[1], rl[2]*rl[2], rl[3]*rl[3]);
            ro[1] = make_float4(rl[4]*rl[4], rl[5]*rl[5], rl[6]*rl[6], rl[7]*rl[7]);
        }
        __syncthreads();
    }

    // ---- phase3: thread = local t; all 32 j in registers ----
    const int lt = tid;
    float a[32];
    {
        const float4* rr = (const float4*)(r2 + lt * 36);
#pragma unroll
        for (int i = 0; i < 8; ++i) {
            const float4 q4 = rr[i];
            a[4 * i] = q4.x; a[4 * i + 1] = q4.y;
            a[4 * i + 2] = q4.z; a[4 * i + 3] = q4.w;
        }
    }
    const float gu = __expf((float)lt * NLN_G);   // gamma^{-lt}
#pragma unroll
    for (int j = 0; j < 32; ++j) a[j] *= gu;

    // intra-warp inclusive prefix (per j) of u = r^2 * gamma^{-t}
#pragma unroll
    for (int j = 0; j < 32; ++j) {
        float v = a[j];
#pragma unroll
        for (int o = 1; o < 32; o <<= 1) {
            const float n = __shfl_up_sync(0xffffffffu, v, o);
            if (lane >= o) v += n;
        }
        a[j] = v;
    }
    if (lane == 31) {
        float4* wt = (float4*)(wtot + w * 32);
#pragma unroll
        for (int i = 0; i < 8; ++i)
            wt[i] = make_float4(a[4 * i], a[4 * i + 1], a[4 * i + 2], a[4 * i + 3]);
    }
    // decoupled lookback for previous chunk's h (c = slow grid index)
    if (c > 0 && tid == 0) {
        volatile int* f = (volatile int*)&g_flag[b * NCB + c - 1];
        while (*f == 0) { __nanosleep(40); }
    }
    __syncthreads();
    if (tid < 32)
        hps[tid] = (c > 0) ? g_hfull[(b * NCB + c - 1) * DOUT + tid] : 0.f;
    __syncthreads();

    // cross-warp prefix carry
#pragma unroll
    for (int wp = 0; wp < 3; ++wp) {
        if (w > wp) {
            const float4* wt = (const float4*)(wtot + wp * 32);
#pragma unroll
            for (int i = 0; i < 8; ++i) {
                const float4 q4 = wt[i];
                a[4 * i] += q4.x; a[4 * i + 1] += q4.y;
                a[4 * i + 2] += q4.z; a[4 * i + 3] += q4.w;
            }
        }
    }

    const float gl  = __expf(-(float)lt * NLN_G);   // gamma^{lt}
    const float gl1 = gl * GAMMA;                   // gamma^{lt+1}
    const int   tg  = t0 + lt;
    const float sden = (1.f - __expf(-(float)(tg + 1) * NLN_G)) * (1.f / (1.f - GAMMA));
    const float sinv = __fdividef(1.f, sden);

#pragma unroll
    for (int j = 0; j < 32; ++j)
        a[j] = fmaf(gl, a[j], gl1 * hps[j]);        // full h_t[j]

    if (tid == 127) {
        float4* hout = (float4*)&g_hfull[(b * NCB + c) * DOUT];
#pragma unroll
        for (int i = 0; i < 8; ++i)
            hout[i] = make_float4(a[4 * i], a[4 * i + 1], a[4 * i + 2], a[4 * i + 3]);
        __threadfence();
        atomicExch(&g_flag[b * NCB + c], 1);
    }

    // x = log(h/s + eps_h)
#pragma unroll
    for (int j = 0; j < 32; ++j)
        a[j] = __logf(fmaf(a[j], sinv, EPS_H));

    // LayerNorm over 32 register values (lane-local)
    float mu = 0.f;
#pragma unroll
    for (int j = 0; j < 32; ++j) mu += a[j];
    mu *= (1.f / 32.f);
    float var = 0.f;
#pragma unroll
    for (int j = 0; j < 32; ++j) { const float dd = a[j] - mu; var = fmaf(dd, dd, var); }
    var *= (1.f / 32.f);
    const float rs = rsqrtf(var + LN_EPS);

    float l0 = 0.f, l1 = 0.f, l2 = 0.f, l3 = 0.f;
#pragma unroll
    for (int j = 0; j < 32; ++j) {
        const float xn = fmaf((a[j] - mu) * rs, lnw[j], lnb[j]);
        l0 = fmaf(xn, cw[j], l0);
        l1 = fmaf(xn, cw[32 + j], l1);
        l2 = fmaf(xn, cw[64 + j], l2);
        l3 = fmaf(xn, cw[96 + j], l3);
    }

    float4* xo = (float4*)(x_out + ((size_t)(b * T + tg)) * DOUT);
#pragma unroll
    for (int i = 0; i < 8; ++i)
        xo[i] = make_float4(a[4 * i], a[4 * i + 1], a[4 * i + 2], a[4 * i + 3]);
    float4* lo = (float4*)(logits_out + ((size_t)(b * T + tg)) * C);
    lo[0] = make_float4(l0 + cb[0], l1 + cb[1], l2 + cb[2], l3 + cb[3]);
}

// ---------------------------------------------------------------------------
extern "C" void kernel_launch(void* const* d_in, const int* in_sizes, int n_in,
                              void* d_out, int out_size)
{
    const float* z     = (const float*)d_in[0];
    const float* proj  = (const float*)d_in[1];
    const float* ln_w  = (const float*)d_in[2];
    const float* ln_b  = (const float*)d_in[3];
    const float* cls_w = (const float*)d_in[4];
    const float* cls_b = (const float*)d_in[5];

    float* out        = (float*)d_out;
    float* x_out      = out;
    float* logits_out = out + (size_t)B * T * DOUT;

    cudaFuncSetAttribute(k_fused, cudaFuncAttributeMaxDynamicSharedMemorySize,
                         SMEM_BYTES);

    k_stats<<<dim3(B, NCB), 128>>>(z);
    k_fused<<<dim3(B, NCB), 128, SMEM_BYTES>>>(z, proj, ln_w, ln_b, cls_w, cls_b,
                                               x_out, logits_out);
}

// round 9
// speedup vs baseline: 2.6615x; 1.0810x over previous
#include <cuda_runtime.h>
#include <cstdint>

namespace {
constexpr int B = 512, T = 512, D = 128, DOUT = 32, C = 4;
constexpr int NCB = 4;      // chunks over T
constexpr int CTB = 128;    // timesteps per block
constexpr int SUB = 32;     // timesteps per sub-tile
constexpr int NSUB = CTB / SUB;
constexpr float ALPHA  = 0.1f;
constexpr float GAMMA  = 0.9f;
constexpr float EPS    = 1e-5f;
constexpr float EPS_H  = 1e-6f;
constexpr float LN_EPS = 1e-5f;
constexpr float NLN_G  = 0.10536051565782628f;   // -ln(0.9)

constexpr int ZROW = 132;   // ps row pitch (floats)
constexpr int TROW = 36;    // zsT / r2 row pitch (floats)

// smem layout (floats)
constexpr int OFF_PS   = 0;                    // [SUB][ZROW]: v-tile, then psum
constexpr int OFF_ZT   = OFF_PS + SUB * ZROW;  // [D][TROW]: delta2 -> z_tilde (transposed)
constexpr int OFF_P    = OFF_ZT + D * TROW;    // [D][DOUT]: proj
constexpr int OFF_R2   = OFF_P + D * DOUT;     // [CTB][TROW]: r^2
constexpr int OFF_VBAR = OFF_R2 + CTB * TROW;  // [32]
constexpr int OFF_WTOT = OFF_VBAR + 32;        // [4][32]
constexpr int OFF_HP   = OFF_WTOT + 128;       // [32]
constexpr int OFF_LNW  = OFF_HP + 32;          // [32]
constexpr int OFF_LNB  = OFF_LNW + 32;         // [32]
constexpr int OFF_CW   = OFF_LNB + 32;         // [4][32]
constexpr int OFF_CB   = OFF_CW + 128;         // [4]
constexpr int OFF_IT   = OFF_CB + 4;           // [CTB] 1/tau
constexpr int OFF_IT1  = OFF_IT + CTB;         // [CTB] 1/max(tau-1,1)
constexpr int SMEM_FLOATS = OFF_IT1 + CTB;
constexpr int SMEM_BYTES  = SMEM_FLOATS * 4;   // ~73 KB
}

// scratch (static device globals — no allocation)
__device__ float g_s1[B * NCB * D];
__device__ float g_s2[B * NCB * D];
__device__ float g_hfull[B * NCB * DOUT];
__device__ int   g_flag[B * NCB];

__device__ __forceinline__ void fma2(unsigned long long& d,
                                     unsigned long long a,
                                     unsigned long long b,
                                     unsigned long long c)
{
    asm("fma.rn.f32x2 %0, %1, %2, %3;" : "=l"(d) : "l"(a), "l"(b), "l"(c));
}
__device__ __forceinline__ unsigned long long splat2(float a) {
    unsigned long long r;
    asm("mov.b64 %0, {%1, %1};" : "=l"(r) : "f"(a));
    return r;
}

// ---------------------------------------------------------------------------
// K1: per-(b,chunk) sums of z, z^2 (Welford carry) + flag reset
// ---------------------------------------------------------------------------
__global__ __launch_bounds__(128)
void k_stats(const float* __restrict__ z)
{
    const int b = blockIdx.x, c = blockIdx.y, d = threadIdx.x;
    const float* zp = z + ((size_t)(b * T + c * CTB)) * D + d;
    float s1 = 0.f, s2 = 0.f;
#pragma unroll 4
    for (int t = 0; t < CTB; ++t) {
        float zz = zp[(size_t)t * D];
        s1 += zz;
        s2 = fmaf(zz, zz, s2);
    }
    g_s1[(b * NCB + c) * D + d] = s1;
    g_s2[(b * NCB + c) * D + d] = s2;
    if (d == 0) g_flag[b * NCB + c] = 0;
}

// ---------------------------------------------------------------------------
// K2: fused normalize + project + h-prefix + tail; block per (b, 128-t chunk)
// ---------------------------------------------------------------------------
__global__ __launch_bounds__(128)
void k_fused(const float* __restrict__ z, const float* __restrict__ proj,
             const float* __restrict__ ln_w, const float* __restrict__ ln_b,
             const float* __restrict__ cls_w, const float* __restrict__ cls_b,
             float* __restrict__ x_out, float* __restrict__ logits_out)
{
    const int b = blockIdx.x, c = blockIdx.y;
    const int tid = threadIdx.x, lane = tid & 31, w = tid >> 5;

    extern __shared__ float sm[];
    float* ps   = sm + OFF_PS;     // v-tile in phase1/1b/1c, psum in phase2
    float* zsT  = sm + OFF_ZT;     // [d][t], pitch TROW
    float* Psm  = sm + OFF_P;      // proj [d][j], pitch 32
    float* r2   = sm + OFF_R2;
    float* vbar = sm + OFF_VBAR;
    float* wtot = sm + OFF_WTOT;
    float* hps  = sm + OFF_HP;
    float* lnw  = sm + OFF_LNW;
    float* lnb  = sm + OFF_LNB;
    float* cw   = sm + OFF_CW;
    float* cb   = sm + OFF_CB;
    float* itab = sm + OFF_IT;
    float* itab1= sm + OFF_IT1;

    const int t0 = c * CTB;

    // ---- params + tables + proj into smem ----
#pragma unroll
    for (int i = 0; i < D * DOUT / 128; ++i)
        Psm[i * 128 + tid] = proj[i * 128 + tid];
    if (tid < 32) { lnw[tid] = ln_w[tid]; lnb[tid] = ln_b[tid]; }
    cw[tid] = cls_w[tid];
    if (tid < 4) cb[tid] = cls_b[tid];
    {
        const float tau = (float)(t0 + tid + 1);
        itab[tid]  = 1.0f / tau;
        itab1[tid] = 1.0f / fmaxf(tau - 1.f, 1.f);
    }

    // ---- Welford carry-in from chunk sums ----
    float s1 = 0.f, s2 = 0.f;
    for (int cp = 0; cp < c; ++cp) {
        s1 += g_s1[(b * NCB + cp) * D + tid];
        s2 += g_s2[(b * NCB + cp) * D + tid];
    }
    const float* zp = z + ((size_t)(b * T + t0)) * D + tid;

    const int tq2 = tid >> 2, jq2 = tid & 3;     // phase1b / 2b mapping
    const int jq = lane >> 3, tq = lane & 7;     // phase2 mapping
    __syncthreads();

    for (int sub = 0; sub < NSUB; ++sub) {
        // ---- phase1: Welford (thread = d) -> zsT[d][t] (transposed), v -> ps ----
#pragma unroll 2
        for (int tg = 0; tg < SUB / 4; ++tg) {
            float4 d2q;
            float* d2a = (float*)&d2q;
#pragma unroll
            for (int i = 0; i < 4; ++i) {
                const int tl = tg * 4 + i;
                const int tb = sub * SUB + tl;
                const float zz = zp[(size_t)tb * D];
                s1 += zz;
                s2 = fmaf(zz, zz, s2);
                const float m = s1 * itab[tb];
                d2a[i] = zz - m;
                ps[tl * ZROW + tid] = fmaf(-s1, m, s2) * itab1[tb];
            }
            *(float4*)(zsT + tid * TROW + tg * 4) = d2q;   // 4-way-conflict STS.128
        }
        __syncthreads();

        // ---- phase1b: vbar per t (4 threads per t) ----
        {
            float p = 0.f;
            const float4* vr = (const float4*)(ps + tq2 * ZROW + jq2 * 32);
#pragma unroll
            for (int i = 0; i < 8; ++i) {
                const float4 q4 = vr[i];
                p += (q4.x + q4.y) + (q4.z + q4.w);
            }
            p += __shfl_xor_sync(0xffffffffu, p, 1);
            p += __shfl_xor_sync(0xffffffffu, p, 2);
            if (jq2 == 0) vbar[tq2] = p * (1.f / 128.f);
        }
        __syncthreads();

        // ---- phase1c: scale zsT row in place (thread = d) ----
#pragma unroll 2
        for (int i = 0; i < 8; ++i) {
            float4 q = *(const float4*)(zsT + tid * TROW + i * 4);
            float* qa = (float*)&q;
#pragma unroll
            for (int k = 0; k < 4; ++k) {
                const int tl = i * 4 + k;
                const float vt = fmaf(ALPHA, vbar[tl],
                                      (1.f - ALPHA) * ps[tl * ZROW + tid]);
                qa[k] *= rsqrtf(vt + EPS);
            }
            *(float4*)(zsT + tid * TROW + i * 4) = q;
        }
        __syncthreads();

        // ---- phase2: GEMM microkernel. warp w: d in [32w,32w+32).
        // thread (jq,tq): 8 j x 4 t tile. per d: 1 z-LDS.128 + 2 P-LDS.128 + 16 fma2
        {
            unsigned long long acc[4][4];
#pragma unroll
            for (int i = 0; i < 4; ++i)
#pragma unroll
                for (int jj = 0; jj < 4; ++jj) acc[i][jj] = 0ull;

            const float* ztw = zsT + (w * 32) * TROW + tq * 4;
            const float* ppw = Psm + (w * 32) * DOUT + jq * 8;
#pragma unroll 4
            for (int d = 0; d < 32; ++d) {
                const float4 zq = *(const float4*)(ztw + d * TROW);
                const ulonglong2 pa = *(const ulonglong2*)(ppw + d * DOUT);
                const unsigned long long z0 = splat2(zq.x), z1 = splat2(zq.y);
                const unsigned long long z2 = splat2(zq.z), z3 = splat2(zq.w);
                fma2(acc[0][0], z0, pa.x, acc[0][0]);
                fma2(acc[0][1], z0, pa.y, acc[0][1]);
                fma2(acc[1][0], z1, pa.x, acc[1][0]);
                fma2(acc[1][1], z1, pa.y, acc[1][1]);
                fma2(acc[2][0], z2, pa.x, acc[2][0]);
                fma2(acc[2][1], z2, pa.y, acc[2][1]);
                fma2(acc[3][0], z3, pa.x, acc[3][0]);
                fma2(acc[3][1], z3, pa.y, acc[3][1]);
                const ulonglong2 pb = *(const ulonglong2*)(ppw + d * DOUT + 4);
                fma2(acc[0][2], z0, pb.x, acc[0][2]);
                fma2(acc[0][3], z0, pb.y, acc[0][3]);
                fma2(acc[1][2], z1, pb.x, acc[1][2]);
                fma2(acc[1][3], z1, pb.y, acc[1][3]);
                fma2(acc[2][2], z2, pb.x, acc[2][2]);
                fma2(acc[2][3], z2, pb.y, acc[2][3]);
                fma2(acc[3][2], z3, pb.x, acc[3][2]);
                fma2(acc[3][3], z3, pb.y, acc[3][3]);
            }
            // store partials: ps[t][w*32 + j]
#pragma unroll
            for (int i = 0; i < 4; ++i) {
                ulonglong2* dst = (ulonglong2*)(ps + (tq * 4 + i) * ZROW + w * 32 + jq * 8);
                dst[0] = make_ulonglong2(acc[i][0], acc[i][1]);
                dst[1] = make_ulonglong2(acc[i][2], acc[i][3]);
            }
        }
        __syncthreads();

        // ---- phase2b: reduce 4 warp partials -> r^2 ----
        {
            const int j0 = jq2 * 8;
            float rl[8];
#pragma unroll
            for (int i = 0; i < 8; ++i) rl[i] = 0.f;
#pragma unroll
            for (int ws = 0; ws < 4; ++ws) {
                const float4* p4 = (const float4*)(ps + tq2 * ZROW + ws * 32 + j0);
                const float4 q0 = p4[0], q1 = p4[1];
                rl[0] += q0.x; rl[1] += q0.y; rl[2] += q0.z; rl[3] += q0.w;
                rl[4] += q1.x; rl[5] += q1.y; rl[6] += q1.z; rl[7] += q1.w;
            }
            float4* ro = (float4*)(r2 + (sub * SUB + tq2) * TROW + j0);
            ro[0] = make_float4(rl[0]*rl[0], rl[1]*rl[1], rl[2]*rl[2], rl[3]*rl[3]);
            ro[1] = make_float4(rl[4]*rl[4], rl[5]*rl[5], rl[6]*rl[6], rl[7]*rl[7]);
        }
        __syncthreads();
    }

    // ---- phase3: thread = local t; all 32 j in registers ----
    const int lt = tid;
    float a[32];
    {
        const float4* rr = (const float4*)(r2 + lt * TROW);
#pragma unroll
        for (int i = 0; i < 8; ++i) {
            const float4 q4 = rr[i];
            a[4 * i] = q4.x; a[4 * i + 1] = q4.y;
            a[4 * i + 2] = q4.z; a[4 * i + 3] = q4.w;
        }
    }
    const float gu = __expf((float)lt * NLN_G);   // gamma^{-lt}
#pragma unroll
    for (int j = 0; j < 32; ++j) a[j] *= gu;

    // intra-warp inclusive prefix (per j)
#pragma unroll
    for (int j = 0; j < 32; ++j) {
        float v = a[j];
#pragma unroll
        for (int o = 1; o < 32; o <<= 1) {
            const float n = __shfl_up_sync(0xffffffffu, v, o);
            if (lane >= o) v += n;
        }
        a[j] = v;
    }
    if (lane == 31) {
        float4* wt = (float4*)(wtot + w * 32);
#pragma unroll
        for (int i = 0; i < 8; ++i)
            wt[i] = make_float4(a[4 * i], a[4 * i + 1], a[4 * i + 2], a[4 * i + 3]);
    }
    // decoupled lookback for previous chunk's h (c = slow grid index)
    if (c > 0 && tid == 0) {
        volatile int* f = (volatile int*)&g_flag[b * NCB + c - 1];
        while (*f == 0) { __nanosleep(40); }
    }
    __syncthreads();
    if (tid < 32)
        hps[tid] = (c > 0) ? g_hfull[(b * NCB + c - 1) * DOUT + tid] : 0.f;
    __syncthreads();

    // cross-warp prefix carry
#pragma unroll
    for (int wp = 0; wp < 3; ++wp) {
        if (w > wp) {
            const float4* wt = (const float4*)(wtot + wp * 32);
#pragma unroll
            for (int i = 0; i < 8; ++i) {
                const float4 q4 = wt[i];
                a[4 * i] += q4.x; a[4 * i + 1] += q4.y;
                a[4 * i + 2] += q4.z; a[4 * i + 3] += q4.w;
            }
        }
    }

    const float gl  = __expf(-(float)lt * NLN_G);   // gamma^{lt}
    const float gl1 = gl * GAMMA;                   // gamma^{lt+1}
    const int   tg  = t0 + lt;
    const float sden = (1.f - __expf(-(float)(tg + 1) * NLN_G)) * (1.f / (1.f - GAMMA));
    const float sinv = __fdividef(1.f, sden);

#pragma unroll
    for (int j = 0; j < 32; ++j)
        a[j] = fmaf(gl, a[j], gl1 * hps[j]);        // full h_t[j]

    if (tid == 127) {
        float4* hout = (float4*)&g_hfull[(b * NCB + c) * DOUT];
#pragma unroll
        for (int i = 0; i < 8; ++i)
            hout[i] = make_float4(a[4 * i], a[4 * i + 1], a[4 * i + 2], a[4 * i + 3]);
        __threadfence();
        atomicExch(&g_flag[b * NCB + c], 1);
    }

    // x = log(h/s + eps_h)
#pragma unroll
    for (int j = 0; j < 32; ++j)
        a[j] = __logf(fmaf(a[j], sinv, EPS_H));

    // LayerNorm (lane-local)
    float mu = 0.f;
#pragma unroll
    for (int j = 0; j < 32; ++j) mu += a[j];
    mu *= (1.f / 32.f);
    float var = 0.f;
#pragma unroll
    for (int j = 0; j < 32; ++j) { const float dd = a[j] - mu; var = fmaf(dd, dd, var); }
    var *= (1.f / 32.f);
    const float rs = rsqrtf(var + LN_EPS);

    float l0 = 0.f, l1 = 0.f, l2 = 0.f, l3 = 0.f;
#pragma unroll
    for (int j = 0; j < 32; ++j) {
        const float xn = fmaf((a[j] - mu) * rs, lnw[j], lnb[j]);
        l0 = fmaf(xn, cw[j], l0);
        l1 = fmaf(xn, cw[32 + j], l1);
        l2 = fmaf(xn, cw[64 + j], l2);
        l3 = fmaf(xn, cw[96 + j], l3);
    }

    float4* xo = (float4*)(x_out + ((size_t)(b * T + tg)) * DOUT);
#pragma unroll
    for (int i = 0; i < 8; ++i)
        xo[i] = make_float4(a[4 * i], a[4 * i + 1], a[4 * i + 2], a[4 * i + 3]);
    float4* lo = (float4*)(logits_out + ((size_t)(b * T + tg)) * C);
    lo[0] = make_float4(l0 + cb[0], l1 + cb[1], l2 + cb[2], l3 + cb[3]);
}

// ---------------------------------------------------------------------------
extern "C" void kernel_launch(void* const* d_in, const int* in_sizes, int n_in,
                              void* d_out, int out_size)
{
    const float* z     = (const float*)d_in[0];
    const float* proj  = (const float*)d_in[1];
    const float* ln_w  = (const float*)d_in[2];
    const float* ln_b  = (const float*)d_in[3];
    const float* cls_w = (const float*)d_in[4];
    const float* cls_b = (const float*)d_in[5];

    float* out        = (float*)d_out;
    float* x_out      = out;
    float* logits_out = out + (size_t)B * T * DOUT;

    cudaFuncSetAttribute(k_fused, cudaFuncAttributeMaxDynamicSharedMemorySize,
                         SMEM_BYTES);

    k_stats<<<dim3(B, NCB), 128>>>(z);
    k_fused<<<dim3(B, NCB), 128, SMEM_BYTES>>>(z, proj, ln_w, ln_b, cls_w, cls_b,
                                               x_out, logits_out);
}